// round 2
// baseline (speedup 1.0000x reference)
#include <cuda_runtime.h>
#include <cstddef>

#define NN 8192
#define DD 512
#define SCALE 0.04419417382415922f   // 1/sqrt(512)
#define NEGV  -1000000.0f

// ---------------- scratch (static __device__ — no allocs allowed) ----------
__device__ float g_q[NN * DD];
__device__ float g_k[NN * DD];
__device__ float g_v[NN * DD];
__device__ float g_S[(size_t)NN * NN];                // 256 MB score / prob matrix
__device__ unsigned int g_adj[(size_t)NN * NN / 32];  // 8 MB adjacency bitmask
__device__ float g_invsum[NN];
__device__ int g_is64;                                // edge_index dtype flag

// ---------------- edge dtype detection -------------------------------------
// int64 edges (values < 2^31): every odd 32-bit word is the zero high-half.
// int32 edges: odd words are real indices; all-zero prob ~ 8192^-512 ~ 0.
__global__ void detect_kernel(const unsigned int* __restrict__ w) {
    __shared__ unsigned int red[256];
    unsigned int acc = 0;
    // scan odd words among the first 2048 32-bit words (always in-bounds:
    // buffer is >= 524288 words for either dtype)
    for (int i = threadIdx.x; i < 1024; i += 256) acc |= w[2 * i + 1];
    red[threadIdx.x] = acc;
    __syncthreads();
    #pragma unroll
    for (int s = 128; s > 0; s >>= 1) {
        if (threadIdx.x < s) red[threadIdx.x] |= red[threadIdx.x + s];
        __syncthreads();
    }
    if (threadIdx.x == 0) g_is64 = (red[0] == 0u) ? 1 : 0;
}

// ---------------- adjacency ------------------------------------------------
__global__ void adj_zero_kernel() {
    int i = blockIdx.x * blockDim.x + threadIdx.x;
    if (i < NN * (NN / 32)) g_adj[i] = 0u;
}

__global__ void adj_scatter_kernel(const void* __restrict__ ei, int E) {
    int e = blockIdx.x * blockDim.x + threadIdx.x;
    if (e >= E) return;
    int r, c;
    if (g_is64) {
        const long long* p = (const long long*)ei;
        r = (int)p[e];
        c = (int)p[(size_t)E + e];
    } else {
        const int* p = (const int*)ei;
        r = p[e];
        c = p[(size_t)E + e];
    }
    if ((unsigned)r >= NN || (unsigned)c >= NN) return;   // never crash
    size_t bit = (size_t)r * NN + (size_t)c;
    atomicOr(&g_adj[bit >> 5], 1u << (bit & 31));
}

// ---------------- SGEMM: 128x128 block, BK=8, 256 threads, 8x8 microtile ---
enum { EPI_BIAS = 0, EPI_MASK = 1, EPI_ROWSCALE = 2 };

template<bool TRANS_B, int EPI>
__global__ __launch_bounds__(256)
void sgemm_kernel(const float* __restrict__ A,
                  const float* __restrict__ B,
                  const float* __restrict__ bias,
                  float* __restrict__ C,
                  int M, int Nc, int K)
{
    __shared__ __align__(16) float As[8][128];
    __shared__ __align__(16) float Bs[8][128];

    const int t  = threadIdx.x;
    const int tx = t & 15;        // 0..15  -> column groups
    const int ty = t >> 4;        // 0..15  -> row groups
    const int bm = blockIdx.y;
    const int bn = blockIdx.x;

    const int row_a  = t >> 1;    // 0..127 (A / trans-B tile row)
    const int half_a = t & 1;     // which float4 of the 8-wide row
    const int rb = t >> 5;        // 0..7  (NT B tile row)
    const int cb = t & 31;        // 0..31 (NT B tile float4 col)

    float acc[8][8];
    #pragma unroll
    for (int i = 0; i < 8; i++)
        #pragma unroll
        for (int j = 0; j < 8; j++) acc[i][j] = 0.0f;

    for (int kt = 0; kt < K; kt += 8) {
        float4 av = *(const float4*)&A[(size_t)(bm * 128 + row_a) * K + kt + half_a * 4];
        float4 bv;
        if (TRANS_B) {
            bv = *(const float4*)&B[(size_t)(bn * 128 + row_a) * K + kt + half_a * 4];
        } else {
            bv = *(const float4*)&B[(size_t)(kt + rb) * Nc + bn * 128 + cb * 4];
        }

        __syncthreads();   // previous iteration's compute done before overwrite

        As[half_a * 4 + 0][row_a] = av.x;
        As[half_a * 4 + 1][row_a] = av.y;
        As[half_a * 4 + 2][row_a] = av.z;
        As[half_a * 4 + 3][row_a] = av.w;
        if (TRANS_B) {
            Bs[half_a * 4 + 0][row_a] = bv.x;
            Bs[half_a * 4 + 1][row_a] = bv.y;
            Bs[half_a * 4 + 2][row_a] = bv.z;
            Bs[half_a * 4 + 3][row_a] = bv.w;
        } else {
            *(float4*)&Bs[rb][cb * 4] = bv;
        }
        __syncthreads();

        #pragma unroll
        for (int kk = 0; kk < 8; kk++) {
            float4 a0 = *(const float4*)&As[kk][ty * 4];
            float4 a1 = *(const float4*)&As[kk][ty * 4 + 64];
            float4 b0 = *(const float4*)&Bs[kk][tx * 4];
            float4 b1 = *(const float4*)&Bs[kk][tx * 4 + 64];
            float a[8] = {a0.x, a0.y, a0.z, a0.w, a1.x, a1.y, a1.z, a1.w};
            float b[8] = {b0.x, b0.y, b0.z, b0.w, b1.x, b1.y, b1.z, b1.w};
            #pragma unroll
            for (int i = 0; i < 8; i++)
                #pragma unroll
                for (int j = 0; j < 8; j++)
                    acc[i][j] += a[i] * b[j];
        }
    }

    #pragma unroll
    for (int i = 0; i < 8; i++) {
        int m = bm * 128 + ((i < 4) ? (ty * 4 + i) : (64 + ty * 4 + (i - 4)));
        #pragma unroll
        for (int j = 0; j < 8; j++) {
            int n = bn * 128 + ((j < 4) ? (tx * 4 + j) : (64 + tx * 4 + (j - 4)));
            float v = acc[i][j];
            size_t idx = (size_t)m * Nc + n;
            if (EPI == EPI_BIAS) {
                C[idx] = v + bias[n];
            } else if (EPI == EPI_MASK) {
                unsigned w = g_adj[idx >> 5];
                C[idx] = ((w >> (n & 31)) & 1u) ? v * SCALE : NEGV;
            } else {
                C[idx] = v * g_invsum[m];
            }
        }
    }
}

// ---------------- row softmax (2 passes; P left unnormalized) --------------
__global__ __launch_bounds__(256)
void softmax_kernel() {
    const int r = blockIdx.x;
    float* __restrict__ row = &g_S[(size_t)r * NN];
    const int t = threadIdx.x;
    __shared__ float red[256];

    float mx = -3.4e38f;
    for (int c = t; c < NN; c += 256) mx = fmaxf(mx, row[c]);
    red[t] = mx;
    __syncthreads();
    #pragma unroll
    for (int s = 128; s > 0; s >>= 1) {
        if (t < s) red[t] = fmaxf(red[t], red[t + s]);
        __syncthreads();
    }
    mx = red[0];
    __syncthreads();

    float sum = 0.0f;
    for (int c = t; c < NN; c += 256) {
        float e = __expf(row[c] - mx);
        row[c] = e;               // unnormalized prob; 1/sum folded into PV GEMM
        sum += e;
    }
    red[t] = sum;
    __syncthreads();
    #pragma unroll
    for (int s = 128; s > 0; s >>= 1) {
        if (t < s) red[t] += red[t + s];
        __syncthreads();
    }
    if (t == 0) g_invsum[r] = 1.0f / red[0];
}

// ---------------- launch ---------------------------------------------------
extern "C" void kernel_launch(void* const* d_in, const int* in_sizes, int n_in,
                              void* d_out, int out_size)
{
    const float* x  = (const float*)d_in[0];
    const void*  ei = d_in[1];
    const float* Wq = (const float*)d_in[2];
    const float* bq = (const float*)d_in[3];
    const float* Wk = (const float*)d_in[4];
    const float* bk = (const float*)d_in[5];
    const float* Wv = (const float*)d_in[6];
    const float* bv = (const float*)d_in[7];
    float* out = (float*)d_out;
    const int E = in_sizes[1] / 2;

    float *pq, *pk, *pv, *pS;
    cudaGetSymbolAddress((void**)&pq, g_q);
    cudaGetSymbolAddress((void**)&pk, g_k);
    cudaGetSymbolAddress((void**)&pv, g_v);
    cudaGetSymbolAddress((void**)&pS, g_S);

    // 1. adjacency bitmask
    detect_kernel<<<1, 256>>>((const unsigned int*)ei);
    adj_zero_kernel<<<(NN * (NN / 32) + 255) / 256, 256>>>();
    adj_scatter_kernel<<<(E + 255) / 256, 256>>>(ei, E);

    // 2. QKV projections: [8192,512] x [512,512] + bias
    dim3 gProj(DD / 128, NN / 128);
    sgemm_kernel<false, EPI_BIAS><<<gProj, 256>>>(x, Wq, bq, pq, NN, DD, DD);
    sgemm_kernel<false, EPI_BIAS><<<gProj, 256>>>(x, Wk, bk, pk, NN, DD, DD);
    sgemm_kernel<false, EPI_BIAS><<<gProj, 256>>>(x, Wv, bv, pv, NN, DD, DD);

    // 3. S = (q @ k^T) * scale, masked via adjacency bits (fused epilogue)
    dim3 gS(NN / 128, NN / 128);
    sgemm_kernel<true, EPI_MASK><<<gS, 256>>>(pq, pk, nullptr, pS, NN, NN, DD);

    // 4. row softmax (writes unnormalized exp; records 1/rowsum)
    softmax_kernel<<<NN, 256>>>();

    // 5. out = P @ v, scaled by 1/rowsum in epilogue
    dim3 gO(DD / 128, NN / 128);
    sgemm_kernel<false, EPI_ROWSCALE><<<gO, 256>>>(pS, pv, nullptr, out, NN, DD, NN);
}

// round 3
// speedup vs baseline: 7.6717x; 7.6717x over previous
#include <cuda_runtime.h>
#include <cstddef>

#define NN 8192
#define DD 512
#define SCALE 0.04419417382415922f   // 1/sqrt(512)

// ---------------- scratch (static __device__ — no allocs allowed) ----------
__device__ float g_q[NN * DD];
__device__ float g_k[NN * DD];
__device__ float g_v[NN * DD];
__device__ float g_sc_spill[(size_t)NN * NN / 8];     // 32 MB: score spill for deg>2048 rows
__device__ unsigned int g_adj[(size_t)NN * NN / 32];  // 8 MB adjacency bitmask
__device__ float g_vpart[64 * DD];
__device__ float g_vmean[DD];
__device__ int g_is64;

// ---------------- edge dtype detection -------------------------------------
__global__ void detect_kernel(const unsigned int* __restrict__ w) {
    __shared__ unsigned int red[256];
    unsigned int acc = 0;
    for (int i = threadIdx.x; i < 1024; i += 256) acc |= w[2 * i + 1];
    red[threadIdx.x] = acc;
    __syncthreads();
    #pragma unroll
    for (int s = 128; s > 0; s >>= 1) {
        if (threadIdx.x < s) red[threadIdx.x] |= red[threadIdx.x + s];
        __syncthreads();
    }
    if (threadIdx.x == 0) g_is64 = (red[0] == 0u) ? 1 : 0;
}

// ---------------- adjacency ------------------------------------------------
__global__ void adj_zero_kernel() {
    int i = blockIdx.x * blockDim.x + threadIdx.x;
    if (i < NN * (NN / 32)) g_adj[i] = 0u;
}

__global__ void adj_scatter_kernel(const void* __restrict__ ei, int E) {
    int e = blockIdx.x * blockDim.x + threadIdx.x;
    if (e >= E) return;
    int r, c;
    if (g_is64) {
        const long long* p = (const long long*)ei;
        r = (int)p[e];
        c = (int)p[(size_t)E + e];
    } else {
        const int* p = (const int*)ei;
        r = p[e];
        c = p[(size_t)E + e];
    }
    if ((unsigned)r >= NN || (unsigned)c >= NN) return;
    size_t bit = (size_t)r * NN + (size_t)c;
    atomicOr(&g_adj[bit >> 5], 1u << (bit & 31));
}

// ---------------- SGEMM (QKV projections only) -----------------------------
__global__ __launch_bounds__(256)
void sgemm_bias_kernel(const float* __restrict__ A,
                       const float* __restrict__ B,
                       const float* __restrict__ bias,
                       float* __restrict__ C,
                       int M, int Nc, int K)
{
    __shared__ __align__(16) float As[8][128];
    __shared__ __align__(16) float Bs[8][128];

    const int t  = threadIdx.x;
    const int tx = t & 15;
    const int ty = t >> 4;
    const int bm = blockIdx.y;
    const int bn = blockIdx.x;

    const int row_a  = t >> 1;
    const int half_a = t & 1;
    const int rb = t >> 5;
    const int cb = t & 31;

    float acc[8][8];
    #pragma unroll
    for (int i = 0; i < 8; i++)
        #pragma unroll
        for (int j = 0; j < 8; j++) acc[i][j] = 0.0f;

    for (int kt = 0; kt < K; kt += 8) {
        float4 av = *(const float4*)&A[(size_t)(bm * 128 + row_a) * K + kt + half_a * 4];
        float4 bv = *(const float4*)&B[(size_t)(kt + rb) * Nc + bn * 128 + cb * 4];

        __syncthreads();
        As[half_a * 4 + 0][row_a] = av.x;
        As[half_a * 4 + 1][row_a] = av.y;
        As[half_a * 4 + 2][row_a] = av.z;
        As[half_a * 4 + 3][row_a] = av.w;
        *(float4*)&Bs[rb][cb * 4] = bv;
        __syncthreads();

        #pragma unroll
        for (int kk = 0; kk < 8; kk++) {
            float4 a0 = *(const float4*)&As[kk][ty * 4];
            float4 a1 = *(const float4*)&As[kk][ty * 4 + 64];
            float4 b0 = *(const float4*)&Bs[kk][tx * 4];
            float4 b1 = *(const float4*)&Bs[kk][tx * 4 + 64];
            float a[8] = {a0.x, a0.y, a0.z, a0.w, a1.x, a1.y, a1.z, a1.w};
            float b[8] = {b0.x, b0.y, b0.z, b0.w, b1.x, b1.y, b1.z, b1.w};
            #pragma unroll
            for (int i = 0; i < 8; i++)
                #pragma unroll
                for (int j = 0; j < 8; j++)
                    acc[i][j] += a[i] * b[j];
        }
    }

    #pragma unroll
    for (int i = 0; i < 8; i++) {
        int m = bm * 128 + ((i < 4) ? (ty * 4 + i) : (64 + ty * 4 + (i - 4)));
        #pragma unroll
        for (int j = 0; j < 8; j++) {
            int n = bn * 128 + ((j < 4) ? (tx * 4 + j) : (64 + tx * 4 + (j - 4)));
            C[(size_t)m * Nc + n] = acc[i][j] + bias[n];
        }
    }
}

// ---------------- v column mean (for degree-0 rows), deterministic 2-stage -
__global__ void vmean1_kernel() {
    const int b = blockIdx.x;     // 64 blocks, 128 rows each
    const int t = threadIdx.x;    // 256 threads, 2 dims each
    float s0 = 0.f, s1 = 0.f;
    for (int r = 0; r < 128; r++) {
        const float* v = &g_v[(size_t)(b * 128 + r) * DD];
        s0 += v[t];
        s1 += v[t + 256];
    }
    g_vpart[b * DD + t] = s0;
    g_vpart[b * DD + t + 256] = s1;
}

__global__ void vmean2_kernel() {
    const int t = threadIdx.x;
    float s0 = 0.f, s1 = 0.f;
    for (int b = 0; b < 64; b++) {
        s0 += g_vpart[b * DD + t];
        s1 += g_vpart[b * DD + t + 256];
    }
    g_vmean[t]       = s0 * (1.0f / NN);
    g_vmean[t + 256] = s1 * (1.0f / NN);
}

// ---------------- sparse attention: one block (256 thr) per row -----------
#define SC_CAP 2048

__global__ __launch_bounds__(256)
void spattn_kernel(float* __restrict__ out)
{
    const int i = blockIdx.x;
    const int t = threadIdx.x;
    const int lane = t & 31;
    const int wid  = t >> 5;

    __shared__ __align__(16) float qs[DD];          // 2 KB
    __shared__ int   nbr[NN];                       // 32 KB (worst-case full row)
    __shared__ float sc[SC_CAP];                    // 8 KB (typical path)
    __shared__ int   scan[256];                     // 1 KB
    __shared__ float red[256];                      // 1 KB

    // load q_i
    for (int d = t; d < DD; d += 256) qs[d] = g_q[(size_t)i * DD + d];

    // deterministic neighbor enumeration from bitmask (dedupes edge list)
    unsigned word = g_adj[i * 256 + t];             // one 32-col word per thread
    int pc = __popc(word);
    scan[t] = pc;
    __syncthreads();
    #pragma unroll
    for (int off = 1; off < 256; off <<= 1) {
        int mine = scan[t];
        int add  = (t >= off) ? scan[t - off] : 0;
        __syncthreads();
        scan[t] = mine + add;
        __syncthreads();
    }
    const int deg = scan[255];
    {
        int base = scan[t] - pc;
        unsigned w = word;
        while (w) {
            int b = __ffs(w) - 1;
            w &= w - 1;
            nbr[base++] = t * 32 + b;
        }
    }
    __syncthreads();

    if (deg == 0) {   // all masked -> uniform softmax -> mean of v
        for (int d = t; d < DD; d += 256)
            out[(size_t)i * DD + d] = g_vmean[d];
        return;
    }

    float* scores = (deg <= SC_CAP) ? sc : &g_sc_spill[(size_t)i * NN / 8];

    // SDDMM: warp per neighbor
    for (int s = wid; s < deg; s += 8) {
        const float* kj = &g_k[(size_t)nbr[s] * DD];
        float acc = 0.f;
        #pragma unroll 4
        for (int d = lane; d < DD; d += 32) acc += qs[d] * kj[d];
        #pragma unroll
        for (int o = 16; o > 0; o >>= 1) acc += __shfl_xor_sync(0xffffffffu, acc, o);
        if (lane == 0) scores[s] = acc * SCALE;
    }
    __syncthreads();

    // row max
    float m = -3.4e38f;
    for (int s = t; s < deg; s += 256) m = fmaxf(m, scores[s]);
    red[t] = m;
    __syncthreads();
    #pragma unroll
    for (int s = 128; s > 0; s >>= 1) {
        if (t < s) red[t] = fmaxf(red[t], red[t + s]);
        __syncthreads();
    }
    m = red[0];
    __syncthreads();

    // exp + sum (store unnormalized p)
    float sum = 0.f;
    for (int s = t; s < deg; s += 256) {
        float p = __expf(scores[s] - m);
        scores[s] = p;
        sum += p;
    }
    red[t] = sum;
    __syncthreads();
    #pragma unroll
    for (int s = 128; s > 0; s >>= 1) {
        if (t < s) red[t] += red[t + s];
        __syncthreads();
    }
    const float inv = 1.0f / red[0];
    __syncthreads();

    // out_i = (sum_s p_s * v_{j_s}) * inv ; thread owns dims t and t+256
    float o0 = 0.f, o1 = 0.f;
    for (int s = 0; s < deg; s++) {
        float p = scores[s];
        const float* vj = &g_v[(size_t)nbr[s] * DD];
        o0 += p * vj[t];
        o1 += p * vj[t + 256];
    }
    out[(size_t)i * DD + t]       = o0 * inv;
    out[(size_t)i * DD + t + 256] = o1 * inv;
}

// ---------------- launch ---------------------------------------------------
extern "C" void kernel_launch(void* const* d_in, const int* in_sizes, int n_in,
                              void* d_out, int out_size)
{
    const float* x  = (const float*)d_in[0];
    const void*  ei = d_in[1];
    const float* Wq = (const float*)d_in[2];
    const float* bq = (const float*)d_in[3];
    const float* Wk = (const float*)d_in[4];
    const float* bk = (const float*)d_in[5];
    const float* Wv = (const float*)d_in[6];
    const float* bv = (const float*)d_in[7];
    float* out = (float*)d_out;
    const int E = in_sizes[1] / 2;

    float *pq, *pk, *pv;
    cudaGetSymbolAddress((void**)&pq, g_q);
    cudaGetSymbolAddress((void**)&pk, g_k);
    cudaGetSymbolAddress((void**)&pv, g_v);

    // adjacency bitmask (dedupes edges)
    detect_kernel<<<1, 256>>>((const unsigned int*)ei);
    adj_zero_kernel<<<(NN * (NN / 32) + 255) / 256, 256>>>();
    adj_scatter_kernel<<<(E + 255) / 256, 256>>>(ei, E);

    // QKV projections
    dim3 gProj(DD / 128, NN / 128);
    sgemm_bias_kernel<<<gProj, 256>>>(x, Wq, bq, pq, NN, DD, DD);
    sgemm_bias_kernel<<<gProj, 256>>>(x, Wk, bk, pk, NN, DD, DD);
    sgemm_bias_kernel<<<gProj, 256>>>(x, Wv, bv, pv, NN, DD, DD);

    // column mean of v for degree-0 rows (deterministic)
    vmean1_kernel<<<64, 256>>>();
    vmean2_kernel<<<1, 256>>>();

    // sparse masked attention: SDDMM + softmax + PV, one block per row
    spattn_kernel<<<NN, 256>>>(out);
}